// round 14
// baseline (speedup 1.0000x reference)
#include <cuda_runtime.h>
#include <math.h>

// CNF_9663676416569: vector field + exact divergence via weight-precomputed E.
//
// dx  = tanh(tanh([t,x] @ W1 + b1) @ W2 + b2) @ W3 + b3
// div = sum_j (1-h2_j^2) * sum_m (1-h1_m^2) * E[m,j]
//   where E[m,j] = W2[m,j] * sum_k W1[1+k, m] * W3[j, k]   (weights only)
//
// R14: 512 threads/CTA (16 warps/SM) with half-size per-thread tiles to fix
//      the stall-bound 35% issue rate; keeps SMEM k-tile staging of W2/E
//      (broadcast LDS.128), A-dup h1 layout, col-packed FFMA2, DX replica
//      split. Work per CTA unchanged; eligibility doubled.

#define Hm 512
#define Dm 64
#define MT 32
#define H1P 68          // dup'd h1 pitch: 64 dup floats + 4
#define STP 36          // s_st pitch: 32 rows + 4
#define KT  16          // k-tile staged in SMEM
#define NTHR 512

typedef unsigned long long ull;

#define SGN2  0x8000000080000000ULL
#define ONES2 0x3F8000003F800000ULL

__device__ float g_E[Hm * Hm];                  // f32, non-dup
__device__ __align__(16) ull g_W1d[65 * Hm];    // (w,w) pairs for Phase A
__device__ __align__(16) ull g_W3d[Hm * Dm];    // (w,w) pairs for DX

__device__ __forceinline__ ull pack2(float lo, float hi) {
    ull d; asm("mov.b64 %0, {%1, %2};" : "=l"(d) : "f"(lo), "f"(hi)); return d;
}
__device__ __forceinline__ void unpack2(ull v, float& lo, float& hi) {
    asm("mov.b64 {%0, %1}, %2;" : "=f"(lo), "=f"(hi) : "l"(v));
}
__device__ __forceinline__ void ffma2(ull& d, ull a, ull b) {
    asm("fma.rn.f32x2 %0, %1, %2, %0;" : "+l"(d) : "l"(a), "l"(b));
}
__device__ __forceinline__ ull ffma2o(ull a, ull b, ull c) {
    ull d;
    asm("fma.rn.f32x2 %0, %1, %2, %3;" : "=l"(d) : "l"(a), "l"(b), "l"(c));
    return d;
}
__device__ __forceinline__ void fadd2(ull& d, ull a) {
    asm("add.rn.f32x2 %0, %0, %1;" : "+l"(d) : "l"(a));
}

// ---------------------------------------------------------------------------
// Precompute: E = W2 .* (W1[1:,:]^T @ W3^T)  (f32);  dup W1 and W3.
// ---------------------------------------------------------------------------
__global__ __launch_bounds__(256)
void compute_E_kernel(const float* __restrict__ W1,
                      const float* __restrict__ W2,
                      const float* __restrict__ W3) {
    __shared__ float As[64][33];
    __shared__ float Bs[32][65];
    const int m0 = blockIdx.x * 32;
    const int j0 = blockIdx.y * 32;
    const int tid = threadIdx.x;

    for (int p = tid; p < 64 * 32; p += 256) {
        int i = p >> 5, ml = p & 31;
        As[i][ml] = W1[(1 + i) * Hm + m0 + ml];
    }
    for (int p = tid; p < 32 * 64; p += 256) {
        int i = p & 63, jl = p >> 6;
        Bs[jl][i] = W3[(j0 + jl) * 64 + i];
    }
    __syncthreads();

    const int jl = tid & 31;
    const int mg = tid >> 5;
    float acc[4] = {0.f, 0.f, 0.f, 0.f};
    #pragma unroll
    for (int i = 0; i < 64; i++) {
        float b = Bs[jl][i];
        #pragma unroll
        for (int q = 0; q < 4; q++)
            acc[q] = fmaf(As[i][mg * 4 + q], b, acc[q]);
    }
    #pragma unroll
    for (int q = 0; q < 4; q++) {
        int m = m0 + mg * 4 + q;
        int j = j0 + jl;
        g_E[m * Hm + j] = W2[m * Hm + j] * acc[q];
    }

    if (blockIdx.y == 0) {          // dup W1 columns m0..m0+31
        for (int p = tid; p < 65 * 32; p += 256) {
            int c = p >> 5, ml = p & 31;
            const float w = W1[c * Hm + m0 + ml];
            g_W1d[c * Hm + m0 + ml] = pack2(w, w);
        }
    } else if (blockIdx.y == 1) {   // dup W3 rows m0..m0+31
        for (int p = tid; p < 32 * 64; p += 256) {
            int r = p >> 6, cc = p & 63;
            const float w = W3[(m0 + r) * Dm + cc];
            g_W3d[(m0 + r) * Dm + cc] = pack2(w, w);
        }
    }
}

// ---------------------------------------------------------------------------
// Main kernel: one CTA = 32 batch rows, 512 threads (16 warps), 1 CTA/SM.
// Phase B map: rp = tid&15 (rows 2rp..2rp+1), cg = tid>>4 (cols 8*cg..+7
// within a 256-col chunk; 2 chunks).
// SMEM: s_xaT[65][32], s_h1d[512][68] (dup'd), s_st[256][36],
//       s_w2[KT][256], s_e[KT][256], s_div[32]   (~217 KB)
// ---------------------------------------------------------------------------
__global__ __launch_bounds__(NTHR, 1)
void cnf_main_kernel(const float* __restrict__ t,
                     const float* __restrict__ x,
                     const float* __restrict__ W1,
                     const float* __restrict__ b1,
                     const float* __restrict__ W2,
                     const float* __restrict__ b2,
                     const float* __restrict__ W3,
                     const float* __restrict__ b3,
                     float* __restrict__ out) {
    extern __shared__ float sm[];
    float* s_xaT = sm;                        // 65*32  = 2080
    float* s_h1d = sm + 65 * 32;              // 512*68 = 34816
    float* s_st  = s_h1d + 512 * H1P;         // 256*36 = 9216
    float* s_w2  = s_st + 256 * STP;          // 16*256 = 4096
    float* s_e   = s_w2 + KT * 256;           // 16*256 = 4096
    float* s_div = s_e + KT * 256;            // 32

    const int tid  = threadIdx.x;
    const int row0 = blockIdx.x * MT;

    if (tid < MT) s_div[tid] = 0.f;

    // ---- load [t, x] tile transposed ----
    const float tval = t[0];
    for (int p = tid; p < 65 * 32; p += NTHR) {
        int c = p >> 5, r = p & 31;
        s_xaT[c * 32 + r] = (c == 0) ? tval
                                     : x[(size_t)(row0 + r) * 65 + (c - 1)];
    }
    __syncthreads();

    // ---- Phase A: H1 = tanh(Xa @ W1 + b1); 1 n per thread; DUP writes ----
    {
        const int n = tid;
        const float bb = b1[n];
        const ull pb = pack2(bb, bb);
        ull acc2[16];
        #pragma unroll
        for (int p = 0; p < 16; p++) acc2[p] = pb;
        #pragma unroll 4
        for (int c = 0; c < 65; c++) {
            const ull pw = g_W1d[c * Hm + n];
            const ull* xa = (const ull*)(s_xaT + c * 32);
            #pragma unroll
            for (int p = 0; p < 16; p++) ffma2(acc2[p], xa[p], pw);
        }
        float* dst = s_h1d + n * H1P;
        #pragma unroll
        for (int p = 0; p < 16; p++) {
            float lo, hi; unpack2(acc2[p], lo, hi);
            const float tl = tanhf(lo), th = tanhf(hi);
            *(float4*)(dst + 4 * p) = make_float4(tl, tl, th, th);
        }
    }
    __syncthreads();

    // ---- Phase B ----
    const int rp = tid & 15;          // row pair: rows 2rp, 2rp+1
    const int cg = tid >> 4;          // 0..31
    const int r0 = rp * 2;
    const int d0 = cg * 8;            // 8 chunk-local cols

    const int cgm = cg & 15;          // DX col group (two kk-half replicas)
    const int d3  = cgm * 4;          // 4 dx cols
    const int kk0 = (cg >> 4) * 128;  // DX kk half (uniform per warp)

    // staging map: 2 float4 per array per thread
    const int sg_row = tid >> 6;             // 0..7 -> rows sg_row, sg_row+8
    const int sg_c   = (tid & 63) * 4;       // col within row

    ull accDX[4];
    #pragma unroll
    for (int j = 0; j < 4; j++) accDX[j] = 0ull;
    float divacc[2] = {0.f, 0.f};

    for (int ch = 0; ch < 2; ch++) {
        const int n0 = ch * 256;

        // init accZ with b2 pairs
        const ulonglong2 bA = *(const ulonglong2*)(b2 + n0 + d0);
        const ulonglong2 bB = *(const ulonglong2*)(b2 + n0 + d0 + 4);
        ull accZ[2][4], accU[2][4];
        #pragma unroll
        for (int i = 0; i < 2; i++) {
            accZ[i][0] = bA.x; accZ[i][1] = bA.y;
            accZ[i][2] = bB.x; accZ[i][3] = bB.y;
            accU[i][0] = 0ull; accU[i][1] = 0ull;
            accU[i][2] = 0ull; accU[i][3] = 0ull;
        }

        const float* __restrict__ srcW = W2  + n0 + sg_c;
        const float* __restrict__ srcE = g_E + n0 + sg_c;

        // preload tile 0 into registers
        float4 pw[2], pe[2];
        #pragma unroll
        for (int q = 0; q < 2; q++) {
            const int kr = sg_row + q * 8;
            pw[q] = *(const float4*)(srcW + (size_t)kr * Hm);
            pe[q] = *(const float4*)(srcE + (size_t)kr * Hm);
        }

        const float* __restrict__ ph = s_h1d + 4 * rp;

        for (int kt = 0; kt < Hm / KT; kt++) {
            __syncthreads();       // previous tile's readers done
            #pragma unroll
            for (int q = 0; q < 2; q++) {
                const int kr = sg_row + q * 8;
                *(float4*)(s_w2 + kr * 256 + sg_c) = pw[q];
                *(float4*)(s_e  + kr * 256 + sg_c) = pe[q];
            }
            __syncthreads();

            // prefetch next tile (clamped address on last iter)
            {
                const int ktn = (kt + 1 < Hm / KT) ? (kt + 1) : kt;
                const int k0n = ktn * KT;
                #pragma unroll
                for (int q = 0; q < 2; q++) {
                    const int kr = k0n + sg_row + q * 8;
                    pw[q] = *(const float4*)(srcW + (size_t)kr * Hm);
                    pe[q] = *(const float4*)(srcE + (size_t)kr * Hm);
                }
            }

            const int k0 = kt * KT;
            #pragma unroll 4
            for (int kk = 0; kk < KT; kk++) {
                const int k = k0 + kk;
                // A: dup'd pairs for rows 2rp, 2rp+1 (one LDS.128)
                const ulonglong2 a01 = *(const ulonglong2*)(ph + k * H1P);
                const ull av[2] = {a01.x, a01.y};
                ull gv[2];
                #pragma unroll
                for (int i = 0; i < 2; i++)
                    gv[i] = ffma2o(av[i], av[i] ^ SGN2, ONES2);

                // B: broadcast LDS.128 of staged tiles
                const ulonglong2 wA = *(const ulonglong2*)(s_w2 + kk * 256 + d0);
                const ulonglong2 wB = *(const ulonglong2*)(s_w2 + kk * 256 + d0 + 4);
                const ulonglong2 eA = *(const ulonglong2*)(s_e  + kk * 256 + d0);
                const ulonglong2 eB = *(const ulonglong2*)(s_e  + kk * 256 + d0 + 4);

                #pragma unroll
                for (int i = 0; i < 2; i++) {
                    ffma2(accZ[i][0], av[i], wA.x);
                    ffma2(accZ[i][1], av[i], wA.y);
                    ffma2(accZ[i][2], av[i], wB.x);
                    ffma2(accZ[i][3], av[i], wB.y);
                    ffma2(accU[i][0], gv[i], eA.x);
                    ffma2(accU[i][1], gv[i], eA.y);
                    ffma2(accU[i][2], gv[i], eB.x);
                    ffma2(accU[i][3], gv[i], eB.y);
                }
            }
        }

        // h2 / g2 / div partials; stage h2 transposed [col][row]
        float h2v[8][2];                 // [chunk-local col j][row i]
        #pragma unroll
        for (int i = 0; i < 2; i++) {
            float dvi = 0.f;
            #pragma unroll
            for (int jp = 0; jp < 4; jp++) {
                float zl, zh, ul, uh;
                unpack2(accZ[i][jp], zl, zh);
                unpack2(accU[i][jp], ul, uh);
                const float hl = tanhf(zl), hh = tanhf(zh);
                dvi = fmaf(fmaf(-hl, hl, 1.f), ul, dvi);
                dvi = fmaf(fmaf(-hh, hh, 1.f), uh, dvi);
                h2v[2 * jp][i]     = hl;
                h2v[2 * jp + 1][i] = hh;
            }
            divacc[i] += dvi;
        }
        __syncthreads();   // protect s_st from previous readers
        #pragma unroll
        for (int j = 0; j < 8; j++)
            *(float2*)(s_st + (d0 + j) * STP + r0) =
                make_float2(h2v[j][0], h2v[j][1]);
        __syncthreads();

        // accDX += h2_chunk[:, kk0:kk0+128] @ W3[n0+kk0 : n0+kk0+128, d3:d3+4]
        const ulonglong2* __restrict__ pW3 =
            (const ulonglong2*)g_W3d + (d3 >> 1);
        #pragma unroll 8
        for (int kk = 0; kk < 128; kk++) {
            const int kc = kk0 + kk;
            const ull a = *(const ull*)(s_st + kc * STP + r0);
            const ulonglong2 w0 = pW3[(size_t)(n0 + kc) * 32];
            const ulonglong2 w1 = pW3[(size_t)(n0 + kc) * 32 + 1];
            ffma2(accDX[0], a, w0.x); ffma2(accDX[1], a, w0.y);
            ffma2(accDX[2], a, w1.x); ffma2(accDX[3], a, w1.y);
        }
        __syncthreads();
    }

    // ---- DX replica reduction (cg>=16 half adds into cg<16 half) ----
    ull* s_red = (ull*)s_st;
    if (cg >= 16) {
        ull* dst = s_red + ((size_t)(cgm * 16 + rp)) * 4;
        #pragma unroll
        for (int j = 0; j < 4; j++) dst[j] = accDX[j];
    }
    __syncthreads();
    if (cg < 16) {
        const ull* src = s_red + ((size_t)(cgm * 16 + rp)) * 4;
        #pragma unroll
        for (int j = 0; j < 4; j++) fadd2(accDX[j], src[j]);
    }

    // ---- epilogue ----
    atomicAdd(&s_div[r0],     divacc[0]);
    atomicAdd(&s_div[r0 + 1], divacc[1]);

    if (cg < 16) {
        const float4 b3v = *(const float4*)(b3 + d3);
        float v[2][4];
        #pragma unroll
        for (int j = 0; j < 4; j++) unpack2(accDX[j], v[0][j], v[1][j]);
        #pragma unroll
        for (int s = 0; s < 2; s++) {
            const size_t ro = (size_t)(row0 + r0 + s) * 65 + d3;
            out[ro + 0] = v[s][0] + b3v.x;
            out[ro + 1] = v[s][1] + b3v.y;
            out[ro + 2] = v[s][2] + b3v.z;
            out[ro + 3] = v[s][3] + b3v.w;
        }
    }
    __syncthreads();
    if (tid < MT)
        out[(size_t)(row0 + tid) * 65 + 64] = s_div[tid];
}

// ---------------------------------------------------------------------------
extern "C" void kernel_launch(void* const* d_in, const int* in_sizes, int n_in,
                              void* d_out, int out_size) {
    const float* t  = (const float*)d_in[0];
    const float* x  = (const float*)d_in[1];
    const float* W1 = (const float*)d_in[2];
    const float* b1 = (const float*)d_in[3];
    const float* W2 = (const float*)d_in[4];
    const float* b2 = (const float*)d_in[5];
    const float* W3 = (const float*)d_in[6];
    const float* b3 = (const float*)d_in[7];
    float* out = (float*)d_out;

    compute_E_kernel<<<dim3(16, 16), 256>>>(W1, W2, W3);

    const int smem_bytes =
        (65 * 32 + 512 * H1P + 256 * STP + 2 * KT * 256 + 32) *
        (int)sizeof(float);
    cudaFuncSetAttribute(cnf_main_kernel,
                         cudaFuncAttributeMaxDynamicSharedMemorySize, smem_bytes);
    cnf_main_kernel<<<8192 / MT, NTHR, smem_bytes>>>(t, x, W1, b1, W2, b2,
                                                     W3, b3, out);
}

// round 15
// speedup vs baseline: 1.5540x; 1.5540x over previous
#include <cuda_runtime.h>
#include <math.h>

// CNF_9663676416569: vector field + exact divergence via weight-precomputed E.
//
// dx  = tanh(tanh([t,x] @ W1 + b1) @ W2 + b2) @ W3 + b3
// div = sum_j (1-h2_j^2) * sum_m (1-h1_m^2) * E[m,j]
//   where E[m,j] = W2[m,j] * sum_k W1[1+k, m] * W3[j, k]   (weights only)
//
// R15: tf32 mma.sync.m16n8k8 tensor cores for the Z2 (2-pass split-A for
//      accuracy) and U (single-pass) GEMMs. B operands pre-rounded to tf32
//      with cvt.rna (unbiased). Phase A / DX stay FFMA2. 256 thr, MT=32.

#define Hm 512
#define Dm 64
#define MT 32
#define H1P 36          // s_h1 pitch ([k][m], fp32, non-dup)
#define STP 36          // s_st pitch ([col][row])
#define KT  16          // staged k-tile
#define BNP 260         // staged B pitch (256 + 4)

typedef unsigned long long ull;
typedef unsigned int u32;

__device__ float g_W2t[Hm * Hm];                // tf32-rounded W2
__device__ float g_Et [Hm * Hm];                // tf32-rounded E
__device__ __align__(16) ull g_W1d[65 * Hm];    // (w,w) pairs for Phase A
__device__ __align__(16) ull g_W3d[Hm * Dm];    // (w,w) pairs for DX

__device__ __forceinline__ ull pack2(float lo, float hi) {
    ull d; asm("mov.b64 %0, {%1, %2};" : "=l"(d) : "f"(lo), "f"(hi)); return d;
}
__device__ __forceinline__ void unpack2(ull v, float& lo, float& hi) {
    asm("mov.b64 {%0, %1}, %2;" : "=f"(lo), "=f"(hi) : "l"(v));
}
__device__ __forceinline__ void ffma2(ull& d, ull a, ull b) {
    asm("fma.rn.f32x2 %0, %1, %2, %0;" : "+l"(d) : "l"(a), "l"(b));
}
__device__ __forceinline__ u32 f2tf32(float f) {
    u32 r; asm("cvt.rna.tf32.f32 %0, %1;" : "=r"(r) : "f"(f)); return r;
}
__device__ __forceinline__ void mma_tf32(float* d, const u32* a, const u32* b) {
    asm volatile(
        "mma.sync.aligned.m16n8k8.row.col.f32.tf32.tf32.f32 "
        "{%0,%1,%2,%3}, {%4,%5,%6,%7}, {%8,%9}, {%0,%1,%2,%3};\n"
        : "+f"(d[0]), "+f"(d[1]), "+f"(d[2]), "+f"(d[3])
        : "r"(a[0]), "r"(a[1]), "r"(a[2]), "r"(a[3]), "r"(b[0]), "r"(b[1]));
}

// ---------------------------------------------------------------------------
// Precompute: E = W2 .* (W1[1:,:]^T @ W3^T); write tf32-rounded W2/E,
// duplicated W1 (Phase A) and W3 (DX).
// ---------------------------------------------------------------------------
__global__ __launch_bounds__(256)
void compute_E_kernel(const float* __restrict__ W1,
                      const float* __restrict__ W2,
                      const float* __restrict__ W3) {
    __shared__ float As[64][33];
    __shared__ float Bs[32][65];
    const int m0 = blockIdx.x * 32;
    const int j0 = blockIdx.y * 32;
    const int tid = threadIdx.x;

    for (int p = tid; p < 64 * 32; p += 256) {
        int i = p >> 5, ml = p & 31;
        As[i][ml] = W1[(1 + i) * Hm + m0 + ml];
    }
    for (int p = tid; p < 32 * 64; p += 256) {
        int i = p & 63, jl = p >> 6;
        Bs[jl][i] = W3[(j0 + jl) * 64 + i];
    }
    __syncthreads();

    const int jl = tid & 31;
    const int mg = tid >> 5;
    float acc[4] = {0.f, 0.f, 0.f, 0.f};
    #pragma unroll
    for (int i = 0; i < 64; i++) {
        float b = Bs[jl][i];
        #pragma unroll
        for (int q = 0; q < 4; q++)
            acc[q] = fmaf(As[i][mg * 4 + q], b, acc[q]);
    }
    #pragma unroll
    for (int q = 0; q < 4; q++) {
        int m = m0 + mg * 4 + q;
        int j = j0 + jl;
        const float w2 = W2[m * Hm + j];
        g_W2t[m * Hm + j] = __uint_as_float(f2tf32(w2));
        g_Et [m * Hm + j] = __uint_as_float(f2tf32(w2 * acc[q]));
    }

    if (blockIdx.y == 0) {          // dup W1 columns m0..m0+31
        for (int p = tid; p < 65 * 32; p += 256) {
            int c = p >> 5, ml = p & 31;
            const float w = W1[c * Hm + m0 + ml];
            g_W1d[c * Hm + m0 + ml] = pack2(w, w);
        }
    } else if (blockIdx.y == 1) {   // dup W3 rows m0..m0+31
        for (int p = tid; p < 32 * 64; p += 256) {
            int r = p >> 6, cc = p & 63;
            const float w = W3[(m0 + r) * Dm + cc];
            g_W3d[(m0 + r) * Dm + cc] = pack2(w, w);
        }
    }
}

// ---------------------------------------------------------------------------
// Main kernel: one CTA = 32 batch rows, 256 threads (8 warps), 1 CTA/SM.
// Z/U GEMMs: warp (mw = wid&1 -> m0 = 16mw, nw = wid>>1 -> cols 64nw..+63
// within a 256-col chunk) via mma.sync m16n8k8 tf32.
// SMEM: s_xaT[65][32], s_h1[512][36] fp32 [k][m], s_st[256][36],
//       s_w2t[KT][260], s_et[KT][260], s_div[32]  (~152 KB)
// ---------------------------------------------------------------------------
__global__ __launch_bounds__(256, 1)
void cnf_main_kernel(const float* __restrict__ t,
                     const float* __restrict__ x,
                     const float* __restrict__ W1,
                     const float* __restrict__ b1,
                     const float* __restrict__ W2,
                     const float* __restrict__ b2,
                     const float* __restrict__ W3,
                     const float* __restrict__ b3,
                     float* __restrict__ out) {
    extern __shared__ float sm[];
    float* s_xaT = sm;                        // 65*32  = 2080
    float* s_h1  = sm + 65 * 32;              // 512*36 = 18432
    float* s_st  = s_h1 + 512 * H1P;          // 256*36 = 9216
    float* s_w2t = s_st + 256 * STP;          // 16*260 = 4160
    float* s_et  = s_w2t + KT * BNP;          // 16*260 = 4160
    float* s_div = s_et + KT * BNP;           // 32

    const int tid  = threadIdx.x;
    const int row0 = blockIdx.x * MT;

    if (tid < MT) s_div[tid] = 0.f;

    // ---- load [t, x] tile transposed ----
    const float tval = t[0];
    for (int p = tid; p < 65 * 32; p += 256) {
        int c = p >> 5, r = p & 31;
        s_xaT[c * 32 + r] = (c == 0) ? tval
                                     : x[(size_t)(row0 + r) * 65 + (c - 1)];
    }
    __syncthreads();

    // ---- Phase A: H1 = tanh(Xa @ W1 + b1), FFMA2; store fp32 [n][m] ----
    #pragma unroll
    for (int q = 0; q < 2; q++) {
        const int n = tid + q * 256;
        const float bb = b1[n];
        const ull pb = pack2(bb, bb);
        ull acc2[16];
        #pragma unroll
        for (int p = 0; p < 16; p++) acc2[p] = pb;
        #pragma unroll 4
        for (int c = 0; c < 65; c++) {
            const ull pw = g_W1d[c * Hm + n];
            const ull* xa = (const ull*)(s_xaT + c * 32);
            #pragma unroll
            for (int p = 0; p < 16; p++) ffma2(acc2[p], xa[p], pw);
        }
        float* dst = s_h1 + n * H1P;
        #pragma unroll
        for (int p = 0; p < 16; p++) {
            float lo, hi; unpack2(acc2[p], lo, hi);
            *(float2*)(dst + 2 * p) = make_float2(tanhf(lo), tanhf(hi));
        }
    }
    __syncthreads();

    // ---- Phase B ----
    const int lane = tid & 31;
    const int wid  = tid >> 5;
    const int g    = lane >> 2;       // fragment row within tile
    const int kq   = lane & 3;        // fragment k within tile
    const int m0   = (wid & 1) * 16;  // warp m-base
    const int nwb  = (wid >> 1) * 64; // warp n-base within chunk

    // staging map: 4 float4 per array per thread
    const int sgr = tid >> 6;                // 0..3
    const int sgc = (tid & 63) * 4;

    // DX map (independent)
    const int rp = tid & 15, cgd = tid >> 4;
    const int r0 = rp * 2,   d3  = cgd * 4;

    ull accDX[4] = {0ull, 0ull, 0ull, 0ull};
    float dv0 = 0.f, dv1 = 0.f;

    for (int ch = 0; ch < 2; ch++) {
        const int n0 = ch * 256;

        float accZ[8][4], accU[8][4];
        #pragma unroll
        for (int j = 0; j < 8; j++)
            #pragma unroll
            for (int c = 0; c < 4; c++) { accZ[j][c] = 0.f; accU[j][c] = 0.f; }

        const float* __restrict__ srcW = g_W2t + n0 + sgc;
        const float* __restrict__ srcE = g_Et  + n0 + sgc;

        // preload tile 0
        float4 pw[4], pe[4];
        #pragma unroll
        for (int q = 0; q < 4; q++) {
            const int kr = sgr + q * 4;
            pw[q] = *(const float4*)(srcW + (size_t)kr * Hm);
            pe[q] = *(const float4*)(srcE + (size_t)kr * Hm);
        }

        for (int kt = 0; kt < Hm / KT; kt++) {
            __syncthreads();
            #pragma unroll
            for (int q = 0; q < 4; q++) {
                const int kr = sgr + q * 4;
                *(float4*)(s_w2t + kr * BNP + sgc) = pw[q];
                *(float4*)(s_et  + kr * BNP + sgc) = pe[q];
            }
            __syncthreads();

            {   // prefetch next tile (clamped on last)
                const int ktn = (kt + 1 < Hm / KT) ? (kt + 1) : kt;
                #pragma unroll
                for (int q = 0; q < 4; q++) {
                    const int kr = ktn * KT + sgr + q * 4;
                    pw[q] = *(const float4*)(srcW + (size_t)kr * Hm);
                    pe[q] = *(const float4*)(srcE + (size_t)kr * Hm);
                }
            }

            #pragma unroll
            for (int ks = 0; ks < 2; ks++) {
                const int kl = ks * 8;            // tile-local k base
                const int kb = kt * KT + kl;      // global k base

                // A fragments: h (hi/lo split) and g1 = 1-h^2 (hi only)
                const float h00 = s_h1[(kb + kq)     * H1P + m0 + g];
                const float h10 = s_h1[(kb + kq)     * H1P + m0 + g + 8];
                const float h01 = s_h1[(kb + kq + 4) * H1P + m0 + g];
                const float h11 = s_h1[(kb + kq + 4) * H1P + m0 + g + 8];
                u32 ah[4], al[4], ag[4];
                const float hv[4] = {h00, h10, h01, h11};
                #pragma unroll
                for (int i = 0; i < 4; i++) {
                    ah[i] = f2tf32(hv[i]);
                    al[i] = f2tf32(hv[i] - __uint_as_float(ah[i]));
                    ag[i] = f2tf32(fmaf(-hv[i], hv[i], 1.f));
                }

                #pragma unroll
                for (int j = 0; j < 8; j++) {
                    const int nb = nwb + j * 8 + g;
                    u32 bw[2], be[2];
                    bw[0] = __float_as_uint(s_w2t[(kl + kq)     * BNP + nb]);
                    bw[1] = __float_as_uint(s_w2t[(kl + kq + 4) * BNP + nb]);
                    be[0] = __float_as_uint(s_et [(kl + kq)     * BNP + nb]);
                    be[1] = __float_as_uint(s_et [(kl + kq + 4) * BNP + nb]);
                    mma_tf32(accZ[j], ah, bw);
                    mma_tf32(accZ[j], al, bw);
                    mma_tf32(accU[j], ag, be);
                }
            }
        }

        // ---- chunk epilogue: h2, div partials, stage h2 to s_st ----
        __syncthreads();   // previous s_st readers (DX) done
        #pragma unroll
        for (int j = 0; j < 8; j++) {
            const int col0 = nwb + j * 8 + (lane & 3) * 2;   // chunk-local
            const float b20 = b2[n0 + col0];
            const float b21 = b2[n0 + col0 + 1];
            const float h00 = tanhf(accZ[j][0] + b20);
            const float h01 = tanhf(accZ[j][1] + b21);
            const float h10 = tanhf(accZ[j][2] + b20);
            const float h11 = tanhf(accZ[j][3] + b21);
            dv0 = fmaf(fmaf(-h00, h00, 1.f), accU[j][0], dv0);
            dv0 = fmaf(fmaf(-h01, h01, 1.f), accU[j][1], dv0);
            dv1 = fmaf(fmaf(-h10, h10, 1.f), accU[j][2], dv1);
            dv1 = fmaf(fmaf(-h11, h11, 1.f), accU[j][3], dv1);
            s_st[col0       * STP + m0 + g]     = h00;
            s_st[(col0 + 1) * STP + m0 + g]     = h01;
            s_st[col0       * STP + m0 + g + 8] = h10;
            s_st[(col0 + 1) * STP + m0 + g + 8] = h11;
        }
        __syncthreads();

        // ---- DX: accDX += h2_chunk @ W3[n0 : n0+256, d3:d3+4] (FFMA2) ----
        const ulonglong2* __restrict__ pW3 =
            (const ulonglong2*)g_W3d + (d3 >> 1);
        #pragma unroll 8
        for (int kk = 0; kk < 256; kk++) {
            const ull a = *(const ull*)(s_st + kk * STP + r0);
            const ulonglong2 w0 = pW3[(size_t)(n0 + kk) * 32];
            const ulonglong2 w1 = pW3[(size_t)(n0 + kk) * 32 + 1];
            ffma2(accDX[0], a, w0.x); ffma2(accDX[1], a, w0.y);
            ffma2(accDX[2], a, w1.x); ffma2(accDX[3], a, w1.y);
        }
        __syncthreads();
    }

    // ---- final epilogue ----
    atomicAdd(&s_div[m0 + g],     dv0);
    atomicAdd(&s_div[m0 + g + 8], dv1);

    {
        const float4 b3v = *(const float4*)(b3 + d3);
        float v[2][4];
        #pragma unroll
        for (int j = 0; j < 4; j++) unpack2(accDX[j], v[0][j], v[1][j]);
        #pragma unroll
        for (int s = 0; s < 2; s++) {
            const size_t ro = (size_t)(row0 + r0 + s) * 65 + d3;
            out[ro + 0] = v[s][0] + b3v.x;
            out[ro + 1] = v[s][1] + b3v.y;
            out[ro + 2] = v[s][2] + b3v.z;
            out[ro + 3] = v[s][3] + b3v.w;
        }
    }
    __syncthreads();
    if (tid < MT)
        out[(size_t)(row0 + tid) * 65 + 64] = s_div[tid];
}

// ---------------------------------------------------------------------------
extern "C" void kernel_launch(void* const* d_in, const int* in_sizes, int n_in,
                              void* d_out, int out_size) {
    const float* t  = (const float*)d_in[0];
    const float* x  = (const float*)d_in[1];
    const float* W1 = (const float*)d_in[2];
    const float* b1 = (const float*)d_in[3];
    const float* W2 = (const float*)d_in[4];
    const float* b2 = (const float*)d_in[5];
    const float* W3 = (const float*)d_in[6];
    const float* b3 = (const float*)d_in[7];
    float* out = (float*)d_out;

    compute_E_kernel<<<dim3(16, 16), 256>>>(W1, W2, W3);

    const int smem_bytes =
        (65 * 32 + 512 * H1P + 256 * STP + 2 * KT * BNP + 32) *
        (int)sizeof(float);
    cudaFuncSetAttribute(cnf_main_kernel,
                         cudaFuncAttributeMaxDynamicSharedMemorySize, smem_bytes);
    cnf_main_kernel<<<8192 / MT, 256, smem_bytes>>>(t, x, W1, b1, W2, b2,
                                                    W3, b3, out);
}

// round 16
// speedup vs baseline: 1.6148x; 1.0391x over previous
#include <cuda_runtime.h>
#include <math.h>

// CNF_9663676416569: vector field + exact divergence via weight-precomputed E.
//
// dx  = tanh(tanh([t,x] @ W1 + b1) @ W2 + b2) @ W3 + b3
// div = sum_j (1-h2_j^2) * sum_m (1-h1_m^2) * E[m,j]
//   where E[m,j] = W2[m,j] * sum_k W1[1+k, m] * W3[j, k]   (weights only)
//
// R16: 512 threads (16 warps, 4/SMSP) with m16xn32 warp tiles + double-
//      buffered W2/E staging (1 sync per k-tile, prefetch decoupled from
//      barrier). tf32 mma m16n8k8: Z2 2-pass split-A, U single-pass.
//      Phase A / DX stay FFMA2.

#define Hm 512
#define Dm 64
#define MT 32
#define H1P 36          // s_h1 pitch ([k][m], fp32)
#define STP 36          // s_st pitch ([col][row])
#define KT  16          // staged k-tile
#define BNP 260         // staged B pitch (256 + 4)
#define NTHR 512

typedef unsigned long long ull;
typedef unsigned int u32;

__device__ float g_W2t[Hm * Hm];                // tf32-rounded W2
__device__ float g_Et [Hm * Hm];                // tf32-rounded E
__device__ __align__(16) ull g_W1d[65 * Hm];    // (w,w) pairs for Phase A
__device__ __align__(16) ull g_W3d[Hm * Dm];    // (w,w) pairs for DX

__device__ __forceinline__ ull pack2(float lo, float hi) {
    ull d; asm("mov.b64 %0, {%1, %2};" : "=l"(d) : "f"(lo), "f"(hi)); return d;
}
__device__ __forceinline__ void unpack2(ull v, float& lo, float& hi) {
    asm("mov.b64 {%0, %1}, %2;" : "=f"(lo), "=f"(hi) : "l"(v));
}
__device__ __forceinline__ void ffma2(ull& d, ull a, ull b) {
    asm("fma.rn.f32x2 %0, %1, %2, %0;" : "+l"(d) : "l"(a), "l"(b));
}
__device__ __forceinline__ void fadd2(ull& d, ull a) {
    asm("add.rn.f32x2 %0, %0, %1;" : "+l"(d) : "l"(a));
}
__device__ __forceinline__ u32 f2tf32(float f) {
    u32 r; asm("cvt.rna.tf32.f32 %0, %1;" : "=r"(r) : "f"(f)); return r;
}
__device__ __forceinline__ void mma_tf32(float* d, const u32* a, const u32* b) {
    asm volatile(
        "mma.sync.aligned.m16n8k8.row.col.f32.tf32.tf32.f32 "
        "{%0,%1,%2,%3}, {%4,%5,%6,%7}, {%8,%9}, {%0,%1,%2,%3};\n"
        : "+f"(d[0]), "+f"(d[1]), "+f"(d[2]), "+f"(d[3])
        : "r"(a[0]), "r"(a[1]), "r"(a[2]), "r"(a[3]), "r"(b[0]), "r"(b[1]));
}

// ---------------------------------------------------------------------------
// Precompute: E = W2 .* (W1[1:,:]^T @ W3^T); write tf32-rounded W2/E,
// duplicated W1 (Phase A) and W3 (DX).
// ---------------------------------------------------------------------------
__global__ __launch_bounds__(256)
void compute_E_kernel(const float* __restrict__ W1,
                      const float* __restrict__ W2,
                      const float* __restrict__ W3) {
    __shared__ float As[64][33];
    __shared__ float Bs[32][65];
    const int m0 = blockIdx.x * 32;
    const int j0 = blockIdx.y * 32;
    const int tid = threadIdx.x;

    for (int p = tid; p < 64 * 32; p += 256) {
        int i = p >> 5, ml = p & 31;
        As[i][ml] = W1[(1 + i) * Hm + m0 + ml];
    }
    for (int p = tid; p < 32 * 64; p += 256) {
        int i = p & 63, jl = p >> 6;
        Bs[jl][i] = W3[(j0 + jl) * 64 + i];
    }
    __syncthreads();

    const int jl = tid & 31;
    const int mg = tid >> 5;
    float acc[4] = {0.f, 0.f, 0.f, 0.f};
    #pragma unroll
    for (int i = 0; i < 64; i++) {
        float b = Bs[jl][i];
        #pragma unroll
        for (int q = 0; q < 4; q++)
            acc[q] = fmaf(As[i][mg * 4 + q], b, acc[q]);
    }
    #pragma unroll
    for (int q = 0; q < 4; q++) {
        int m = m0 + mg * 4 + q;
        int j = j0 + jl;
        const float w2 = W2[m * Hm + j];
        g_W2t[m * Hm + j] = __uint_as_float(f2tf32(w2));
        g_Et [m * Hm + j] = __uint_as_float(f2tf32(w2 * acc[q]));
    }

    if (blockIdx.y == 0) {          // dup W1 columns m0..m0+31
        for (int p = tid; p < 65 * 32; p += 256) {
            int c = p >> 5, ml = p & 31;
            const float w = W1[c * Hm + m0 + ml];
            g_W1d[c * Hm + m0 + ml] = pack2(w, w);
        }
    } else if (blockIdx.y == 1) {   // dup W3 rows m0..m0+31
        for (int p = tid; p < 32 * 64; p += 256) {
            int r = p >> 6, cc = p & 63;
            const float w = W3[(m0 + r) * Dm + cc];
            g_W3d[(m0 + r) * Dm + cc] = pack2(w, w);
        }
    }
}

// ---------------------------------------------------------------------------
// Main kernel: one CTA = 32 batch rows, 512 threads (16 warps), 1 CTA/SM.
// Z/U: warp (mw = wid&1 -> m0 = 16mw, ng = wid>>1 -> cols 32ng..+31 within a
// 256-col chunk) via mma.sync m16n8k8 tf32; double-buffered B staging.
// SMEM: s_xaT[65][32], s_h1[512][36], s_st[256][36],
//       s_w2t[2][KT][260], s_et[2][KT][260], s_div[32]  (~186 KB)
// ---------------------------------------------------------------------------
__global__ __launch_bounds__(NTHR, 1)
void cnf_main_kernel(const float* __restrict__ t,
                     const float* __restrict__ x,
                     const float* __restrict__ W1,
                     const float* __restrict__ b1,
                     const float* __restrict__ W2,
                     const float* __restrict__ b2,
                     const float* __restrict__ W3,
                     const float* __restrict__ b3,
                     float* __restrict__ out) {
    extern __shared__ float sm[];
    float* s_xaT = sm;                        // 65*32  = 2080
    float* s_h1  = sm + 65 * 32;              // 512*36 = 18432
    float* s_st  = s_h1 + 512 * H1P;          // 256*36 = 9216
    float* s_w2t = s_st + 256 * STP;          // 2*16*260 = 8320
    float* s_et  = s_w2t + 2 * KT * BNP;      // 2*16*260 = 8320
    float* s_div = s_et + 2 * KT * BNP;       // 32

    const int tid  = threadIdx.x;
    const int row0 = blockIdx.x * MT;

    if (tid < MT) s_div[tid] = 0.f;

    // ---- load [t, x] tile transposed ----
    const float tval = t[0];
    for (int p = tid; p < 65 * 32; p += NTHR) {
        int c = p >> 5, r = p & 31;
        s_xaT[c * 32 + r] = (c == 0) ? tval
                                     : x[(size_t)(row0 + r) * 65 + (c - 1)];
    }
    __syncthreads();

    // ---- Phase A: H1 = tanh(Xa @ W1 + b1); 1 n per thread (FFMA2) ----
    {
        const int n = tid;
        const float bb = b1[n];
        const ull pb = pack2(bb, bb);
        ull acc2[16];
        #pragma unroll
        for (int p = 0; p < 16; p++) acc2[p] = pb;
        #pragma unroll 4
        for (int c = 0; c < 65; c++) {
            const ull pw = g_W1d[c * Hm + n];
            const ull* xa = (const ull*)(s_xaT + c * 32);
            #pragma unroll
            for (int p = 0; p < 16; p++) ffma2(acc2[p], xa[p], pw);
        }
        float* dst = s_h1 + n * H1P;
        #pragma unroll
        for (int p = 0; p < 16; p++) {
            float lo, hi; unpack2(acc2[p], lo, hi);
            *(float2*)(dst + 2 * p) = make_float2(tanhf(lo), tanhf(hi));
        }
    }
    __syncthreads();

    // ---- Phase B ----
    const int lane = tid & 31;
    const int wid  = tid >> 5;
    const int g    = lane >> 2;       // fragment row
    const int kq   = lane & 3;        // fragment k
    const int m0   = (wid & 1) * 16;  // warp m-base
    const int nwb  = (wid >> 1) * 32; // warp n-base within chunk (0..224)

    // staging map: 2 float4 per array per thread (rows sgr, sgr+8)
    const int sgr = tid >> 6;                // 0..7
    const int sgc = (tid & 63) * 4;

    // DX map
    const int rp  = tid & 15, cgd = tid >> 4;   // cgd 0..31
    const int r0  = rp * 2;
    const int cgm = cgd & 15;
    const int d3  = cgm * 4;
    const int kk0 = (cgd >> 4) * 128;

    ull accDX[4] = {0ull, 0ull, 0ull, 0ull};
    float dv0 = 0.f, dv1 = 0.f;

    for (int ch = 0; ch < 2; ch++) {
        const int n0 = ch * 256;

        float accZ[4][4], accU[4][4];
        #pragma unroll
        for (int j = 0; j < 4; j++)
            #pragma unroll
            for (int c = 0; c < 4; c++) { accZ[j][c] = 0.f; accU[j][c] = 0.f; }

        const float* __restrict__ srcW = g_W2t + n0 + sgc;
        const float* __restrict__ srcE = g_Et  + n0 + sgc;

        // preload + stage tile 0 into buffer 0
        float4 pw[2], pe[2];
        #pragma unroll
        for (int q = 0; q < 2; q++) {
            const int kr = sgr + q * 8;
            pw[q] = *(const float4*)(srcW + (size_t)kr * Hm);
            pe[q] = *(const float4*)(srcE + (size_t)kr * Hm);
        }
        #pragma unroll
        for (int q = 0; q < 2; q++) {
            const int kr = sgr + q * 8;
            *(float4*)(s_w2t + kr * BNP + sgc) = pw[q];
            *(float4*)(s_et  + kr * BNP + sgc) = pe[q];
        }

        for (int kt = 0; kt < Hm / KT; kt++) {
            // prefetch tile kt+1 (clamped) — long-latency LDG, consumed
            // only at the STS after this tile's compute
            {
                const int ktn = (kt + 1 < Hm / KT) ? (kt + 1) : kt;
                #pragma unroll
                for (int q = 0; q < 2; q++) {
                    const int kr = ktn * KT + sgr + q * 8;
                    pw[q] = *(const float4*)(srcW + (size_t)kr * Hm);
                    pe[q] = *(const float4*)(srcE + (size_t)kr * Hm);
                }
            }
            __syncthreads();   // STS(kt) visible; compute(kt-1) done everywhere

            const float* bufW = s_w2t + (kt & 1) * KT * BNP;
            const float* bufE = s_et  + (kt & 1) * KT * BNP;

            #pragma unroll
            for (int ks = 0; ks < 2; ks++) {
                const int kl = ks * 8;
                const int kb = kt * KT + kl;

                const float h00 = s_h1[(kb + kq)     * H1P + m0 + g];
                const float h10 = s_h1[(kb + kq)     * H1P + m0 + g + 8];
                const float h01 = s_h1[(kb + kq + 4) * H1P + m0 + g];
                const float h11 = s_h1[(kb + kq + 4) * H1P + m0 + g + 8];
                u32 ah[4], al[4], ag[4];
                const float hv[4] = {h00, h10, h01, h11};
                #pragma unroll
                for (int i = 0; i < 4; i++) {
                    ah[i] = f2tf32(hv[i]);
                    al[i] = f2tf32(hv[i] - __uint_as_float(ah[i]));
                    ag[i] = f2tf32(fmaf(-hv[i], hv[i], 1.f));
                }

                #pragma unroll
                for (int j = 0; j < 4; j++) {
                    const int nb = nwb + j * 8 + g;
                    u32 bw[2], be[2];
                    bw[0] = __float_as_uint(bufW[(kl + kq)     * BNP + nb]);
                    bw[1] = __float_as_uint(bufW[(kl + kq + 4) * BNP + nb]);
                    be[0] = __float_as_uint(bufE[(kl + kq)     * BNP + nb]);
                    be[1] = __float_as_uint(bufE[(kl + kq + 4) * BNP + nb]);
                    mma_tf32(accZ[j], ah, bw);
                    mma_tf32(accZ[j], al, bw);
                    mma_tf32(accU[j], ag, be);
                }
            }

            // stage tile kt+1 into the other buffer (safe: its previous
            // contents were tile kt-1, whose compute finished pre-sync)
            {
                float* dstW = s_w2t + ((kt + 1) & 1) * KT * BNP;
                float* dstE = s_et  + ((kt + 1) & 1) * KT * BNP;
                #pragma unroll
                for (int q = 0; q < 2; q++) {
                    const int kr = sgr + q * 8;
                    *(float4*)(dstW + kr * BNP + sgc) = pw[q];
                    *(float4*)(dstE + kr * BNP + sgc) = pe[q];
                }
            }
        }

        // ---- chunk epilogue: h2, div partials, stage h2 to s_st ----
        __syncthreads();   // previous s_st readers (DX) done
        #pragma unroll
        for (int j = 0; j < 4; j++) {
            const int col0 = nwb + j * 8 + kq * 2;       // chunk-local
            const float b20 = b2[n0 + col0];
            const float b21 = b2[n0 + col0 + 1];
            const float h00 = tanhf(accZ[j][0] + b20);
            const float h01 = tanhf(accZ[j][1] + b21);
            const float h10 = tanhf(accZ[j][2] + b20);
            const float h11 = tanhf(accZ[j][3] + b21);
            dv0 = fmaf(fmaf(-h00, h00, 1.f), accU[j][0], dv0);
            dv0 = fmaf(fmaf(-h01, h01, 1.f), accU[j][1], dv0);
            dv1 = fmaf(fmaf(-h10, h10, 1.f), accU[j][2], dv1);
            dv1 = fmaf(fmaf(-h11, h11, 1.f), accU[j][3], dv1);
            s_st[col0       * STP + m0 + g]     = h00;
            s_st[(col0 + 1) * STP + m0 + g]     = h01;
            s_st[col0       * STP + m0 + g + 8] = h10;
            s_st[(col0 + 1) * STP + m0 + g + 8] = h11;
        }
        __syncthreads();

        // ---- DX: accDX += h2[:, kk0:+128] @ W3[n0+kk0:+128, d3:+4] ----
        const ulonglong2* __restrict__ pW3 =
            (const ulonglong2*)g_W3d + (d3 >> 1);
        #pragma unroll 8
        for (int kk = 0; kk < 128; kk++) {
            const int kc = kk0 + kk;
            const ull a = *(const ull*)(s_st + kc * STP + r0);
            const ulonglong2 w0 = pW3[(size_t)(n0 + kc) * 32];
            const ulonglong2 w1 = pW3[(size_t)(n0 + kc) * 32 + 1];
            ffma2(accDX[0], a, w0.x); ffma2(accDX[1], a, w0.y);
            ffma2(accDX[2], a, w1.x); ffma2(accDX[3], a, w1.y);
        }
        __syncthreads();
    }

    // ---- DX replica reduction (cgd>=16 adds into cgd<16) ----
    ull* s_red = (ull*)s_st;
    if (cgd >= 16) {
        ull* dst = s_red + ((size_t)(cgm * 16 + rp)) * 4;
        #pragma unroll
        for (int j = 0; j < 4; j++) dst[j] = accDX[j];
    }
    __syncthreads();
    if (cgd < 16) {
        const ull* src = s_red + ((size_t)(cgm * 16 + rp)) * 4;
        #pragma unroll
        for (int j = 0; j < 4; j++) fadd2(accDX[j], src[j]);
    }

    // ---- final epilogue ----
    atomicAdd(&s_div[m0 + g],     dv0);
    atomicAdd(&s_div[m0 + g + 8], dv1);

    if (cgd < 16) {
        const float4 b3v = *(const float4*)(b3 + d3);
        float v[2][4];
        #pragma unroll
        for (int j = 0; j < 4; j++) unpack2(accDX[j], v[0][j], v[1][j]);
        #pragma unroll
        for (int s = 0; s < 2; s++) {
            const size_t ro = (size_t)(row0 + r0 + s) * 65 + d3;
            out[ro + 0] = v[s][0] + b3v.x;
            out[ro + 1] = v[s][1] + b3v.y;
            out[ro + 2] = v[s][2] + b3v.z;
            out[ro + 3] = v[s][3] + b3v.w;
        }
    }
    __syncthreads();
    if (tid < MT)
        out[(size_t)(row0 + tid) * 65 + 64] = s_div[tid];
}

// ---------------------------------------------------------------------------
extern "C" void kernel_launch(void* const* d_in, const int* in_sizes, int n_in,
                              void* d_out, int out_size) {
    const float* t  = (const float*)d_in[0];
    const float* x  = (const float*)d_in[1];
    const float* W1 = (const float*)d_in[2];
    const float* b1 = (const float*)d_in[3];
    const float* W2 = (const float*)d_in[4];
    const float* b2 = (const float*)d_in[5];
    const float* W3 = (const float*)d_in[6];
    const float* b3 = (const float*)d_in[7];
    float* out = (float*)d_out;

    compute_E_kernel<<<dim3(16, 16), 256>>>(W1, W2, W3);

    const int smem_bytes =
        (65 * 32 + 512 * H1P + 256 * STP + 4 * KT * BNP + 32) *
        (int)sizeof(float);
    cudaFuncSetAttribute(cnf_main_kernel,
                         cudaFuncAttributeMaxDynamicSharedMemorySize, smem_bytes);
    cnf_main_kernel<<<8192 / MT, NTHR, smem_bytes>>>(t, x, W1, b1, W2, b2,
                                                     W3, b3, out);
}